// round 2
// baseline (speedup 1.0000x reference)
#include <cuda_runtime.h>
#include <cstdint>
#include <cstddef>

#define N_NODES 100000
#define T_SEQ   1024
#define IN_CH   128
#define HID     256
#define G3      768     // 3*HID gate rows

// ---------------- scratch (device globals; no allocations allowed) ----------
#define K1_NCHUNK 37
#define K1_CHUNK  2720  // 85*32, 37*2720 = 100640 >= 100000 (guarded)

__device__ float g_part[K1_NCHUNK * T_SEQ * IN_CH];  // ~19.4 MB partials
__device__ float g_ve[T_SEQ * IN_CH];                // visit_emb [1024,128]
__device__ float g_gx[T_SEQ * G3];                   // input gates [1024,768]
__device__ float g_hs[T_SEQ * HID];                  // hidden states [1024,256]

// ============================================================================
// K1: part[c][t][i] = sum_{n in chunk c} H[n][t] * X[n][i]
// grid (8 t-tiles, 37 n-chunks) = 296 CTAs = exactly 2 waves @ 2 CTA/SM
// ============================================================================
__global__ void __launch_bounds__(256, 2) k1_kernel(const float* __restrict__ H,
                                                    const float* __restrict__ X) {
    __shared__ float Hs[32][128];
    __shared__ float Xs[32][128];
    const int tid = threadIdx.x;
    const int tx = tid & 15, ty = tid >> 4;
    const int t0 = blockIdx.x * 128;
    const int n0 = blockIdx.y * K1_CHUNK;

    float acc[8][8];
#pragma unroll
    for (int i = 0; i < 8; i++)
#pragma unroll
        for (int j = 0; j < 8; j++) acc[i][j] = 0.f;

    for (int nb = 0; nb < K1_CHUNK; nb += 32) {
#pragma unroll
        for (int v = 0; v < 4; v++) {
            int e = tid + v * 256;        // 0..1023 float4 slots
            int row = e >> 5;             // 0..31
            int c = (e & 31) << 2;        // 0..124 step 4
            int n = n0 + nb + row;
            float4 hv = make_float4(0.f, 0.f, 0.f, 0.f);
            float4 xv = make_float4(0.f, 0.f, 0.f, 0.f);
            if (n < N_NODES) {
                hv = *(const float4*)(H + (size_t)n * T_SEQ + t0 + c);
                xv = *(const float4*)(X + (size_t)n * IN_CH + c);
            }
            *(float4*)&Hs[row][c] = hv;
            *(float4*)&Xs[row][c] = xv;
        }
        __syncthreads();
#pragma unroll
        for (int kk = 0; kk < 32; kk++) {
            float a[8], b[8];
            *(float4*)&a[0] = *(const float4*)&Hs[kk][ty * 8];
            *(float4*)&a[4] = *(const float4*)&Hs[kk][ty * 8 + 4];
            *(float4*)&b[0] = *(const float4*)&Xs[kk][tx * 8];
            *(float4*)&b[4] = *(const float4*)&Xs[kk][tx * 8 + 4];
#pragma unroll
            for (int i = 0; i < 8; i++)
#pragma unroll
                for (int j = 0; j < 8; j++)
                    acc[i][j] = fmaf(a[i], b[j], acc[i][j]);
        }
        __syncthreads();
    }

    float* pp = g_part + (size_t)blockIdx.y * (T_SEQ * IN_CH);
#pragma unroll
    for (int i = 0; i < 8; i++) {
        int t = t0 + ty * 8 + i;
#pragma unroll
        for (int j = 0; j < 8; j += 4) {
            *(float4*)&pp[t * IN_CH + tx * 8 + j] =
                make_float4(acc[i][j], acc[i][j + 1], acc[i][j + 2], acc[i][j + 3]);
        }
    }
}

// K1b: ve = sum over 37 chunk partials (deterministic reduce)
__global__ void __launch_bounds__(256) k1_reduce_kernel() {
    int idx = blockIdx.x * blockDim.x + threadIdx.x;   // 0..131071
    float s = 0.f;
#pragma unroll
    for (int c = 0; c < K1_NCHUNK; c++) s += g_part[c * (T_SEQ * IN_CH) + idx];
    g_ve[idx] = s;
}

// ============================================================================
// K2: gx[t][r] = b_ih[r] + sum_k ve[t][k]*w_ih[r][k]
// one block per t; warp per 96 rows; w_ih stays L2-resident, coalesced float4
// ============================================================================
__global__ void __launch_bounds__(256) gx_kernel(const float* __restrict__ w_ih,
                                                 const float* __restrict__ b_ih) {
    const int t = blockIdx.x;
    const int w = threadIdx.x >> 5, l = threadIdx.x & 31;
    float4 vv = *(const float4*)(g_ve + t * IN_CH + l * 4);
    for (int rr = 0; rr < 96; rr++) {
        int r = w * 96 + rr;
        float4 wv = *(const float4*)(w_ih + (size_t)r * IN_CH + l * 4);
        float p = vv.x * wv.x + vv.y * wv.y + vv.z * wv.z + vv.w * wv.w;
#pragma unroll
        for (int o = 16; o; o >>= 1) p += __shfl_xor_sync(0xffffffffu, p, o);
        if (l == 0) g_gx[t * G3 + r] = p + b_ih[r];
    }
}

// ============================================================================
// K3: sequential GRU over T=1024 steps. Cluster of 8 CTAs.
// CTA c owns gate rows {g*256 + c*32 + i : g in {0,1,2}, i in [0,32)} -> 96 rows,
// weights (96x256 fp32, lr-padded to 97 for conflict-free SMEM) loaded once.
// Hidden state broadcast each step via st.shared::cluster; cluster.sync/step.
// ============================================================================
#define GRU_W_STRIDE 97
#define OFF_W    0
#define OFF_H    (256 * GRU_W_STRIDE)          // double-buffered h [2][256]
#define OFF_PART (OFF_H + 512)                 // 96 partial sums
#define OFF_GH   (OFF_PART + 96)               // 96 gate pre-activations
#define OFF_BH   (OFF_GH + 96)                 // 96 b_hh values
#define GRU_SMEM_FLOATS (OFF_BH + 96)
#define GRU_SMEM_BYTES  (GRU_SMEM_FLOATS * 4)

__device__ __forceinline__ void cluster_sync_() {
    asm volatile("barrier.cluster.arrive.aligned;" ::: "memory");
    asm volatile("barrier.cluster.wait.aligned;" ::: "memory");
}
__device__ __forceinline__ void st_remote_f32(uint32_t laddr, uint32_t peer, float v) {
    uint32_t raddr;
    asm volatile("mapa.shared::cluster.u32 %0, %1, %2;"
                 : "=r"(raddr) : "r"(laddr), "r"(peer));
    asm volatile("st.shared::cluster.f32 [%0], %1;" :: "r"(raddr), "f"(v) : "memory");
}

__global__ __launch_bounds__(256, 1) __cluster_dims__(8, 1, 1)
void gru_kernel(const float* __restrict__ w_hh, const float* __restrict__ b_hh) {
    extern __shared__ float sm[];
    const int tid = threadIdx.x;
    const int rank = blockIdx.x;   // grid == one cluster of 8

    // load this CTA's 96 weight rows into SMEM, k-major: sm_w[k*97 + lr]
    for (int idx = tid; idx < 96 * 256; idx += 256) {
        int lr = idx >> 8;         // 0..95
        int k = idx & 255;
        int grow = (lr >> 5) * 256 + rank * 32 + (lr & 31);
        sm[OFF_W + k * GRU_W_STRIDE + lr] = w_hh[(size_t)grow * 256 + k];
    }
    if (tid < 96) {
        int grow = (tid >> 5) * 256 + rank * 32 + (tid & 31);
        sm[OFF_BH + tid] = b_hh[grow];
    }
    sm[OFF_H + tid] = 0.f;         // h0 = 0, both buffers
    sm[OFF_H + 256 + tid] = 0.f;
    __syncthreads();
    cluster_sync_();

    const int lr = tid & 127;      // local row (96 active, 97..127 idle)
    const int half = tid >> 7;     // k-half: [0,128) or [128,256)
    const int hbase = rank * 32;

    for (int t = 0; t < T_SEQ; t++) {
        const int cur = t & 1, nxt = cur ^ 1;

        // prefetch this step's input gates (used after the matvec)
        float gxr = 0.f, gxz = 0.f, gxn = 0.f;
        if (tid < 32) {
            const float* gxt = g_gx + t * G3 + hbase + tid;
            gxr = gxt[0];
            gxz = gxt[256];
            gxn = gxt[512];
        }

        // half-matvec: acc = sum_{k in half} w[lr][k] * h[k]
        float a0 = 0.f, a1 = 0.f, a2 = 0.f, a3 = 0.f;
        if (lr < 96) {
            const float* wp = sm + OFF_W + (half * 128) * GRU_W_STRIDE + lr;
            const float* hp = sm + OFF_H + cur * 256 + half * 128;
#pragma unroll
            for (int k = 0; k < 128; k += 4) {
                a0 = fmaf(wp[(k + 0) * GRU_W_STRIDE], hp[k + 0], a0);
                a1 = fmaf(wp[(k + 1) * GRU_W_STRIDE], hp[k + 1], a1);
                a2 = fmaf(wp[(k + 2) * GRU_W_STRIDE], hp[k + 2], a2);
                a3 = fmaf(wp[(k + 3) * GRU_W_STRIDE], hp[k + 3], a3);
            }
        }
        float acc = (a0 + a1) + (a2 + a3);
        if (half == 1 && lr < 96) sm[OFF_PART + lr] = acc;
        __syncthreads();
        if (half == 0 && lr < 96)
            sm[OFF_GH + lr] = acc + sm[OFF_PART + lr] + sm[OFF_BH + lr];
        __syncthreads();

        if (tid < 32) {
            float ghr = sm[OFF_GH + tid];
            float ghz = sm[OFF_GH + 32 + tid];
            float ghn = sm[OFF_GH + 64 + tid];
            float r = 1.f / (1.f + __expf(-(gxr + ghr)));
            float z = 1.f / (1.f + __expf(-(gxz + ghz)));
            float n = tanhf(gxn + r * ghn);
            float hprev = sm[OFF_H + cur * 256 + hbase + tid];
            float hnew = (1.f - z) * n + z * hprev;
            g_hs[t * HID + hbase + tid] = hnew;
            // broadcast into every CTA's next-buffer h (incl. self)
            uint32_t laddr = (uint32_t)__cvta_generic_to_shared(
                sm + OFF_H + nxt * 256 + hbase + tid);
#pragma unroll
            for (int p = 0; p < 8; p++) st_remote_f32(laddr, (uint32_t)p, hnew);
        }
        cluster_sync_();  // release remote stores / acquire for next read
    }
}

// ============================================================================
// K4: logits = hs @ w_attn; alpha = softmax(logits); out = alpha @ hs
// ============================================================================
__global__ void __launch_bounds__(1024) attn_kernel(const float* __restrict__ w_attn,
                                                    float* __restrict__ out) {
    __shared__ float s_alpha[1024];
    __shared__ float s_red[1024];
    __shared__ float s_wa[256];
    const int tid = threadIdx.x;
    if (tid < 256) s_wa[tid] = w_attn[tid];
    __syncthreads();

    const int w = tid >> 5, l = tid & 31;
    for (int tt = 0; tt < 32; tt++) {
        int t = w * 32 + tt;
        const float* hr = g_hs + t * HID;
        float p = 0.f;
#pragma unroll
        for (int j = 0; j < 8; j++) p = fmaf(hr[l + 32 * j], s_wa[l + 32 * j], p);
#pragma unroll
        for (int o = 16; o; o >>= 1) p += __shfl_xor_sync(0xffffffffu, p, o);
        if (l == 0) s_alpha[t] = p;
    }
    __syncthreads();

    float v = s_alpha[tid];
    s_red[tid] = v;
    __syncthreads();
    for (int s = 512; s; s >>= 1) {
        if (tid < s) s_red[tid] = fmaxf(s_red[tid], s_red[tid + s]);
        __syncthreads();
    }
    float m = s_red[0];
    __syncthreads();
    float e = __expf(v - m);
    s_red[tid] = e;
    __syncthreads();
    for (int s = 512; s; s >>= 1) {
        if (tid < s) s_red[tid] = s_red[tid] + s_red[tid + s];
        __syncthreads();
    }
    float inv = 1.f / s_red[0];
    __syncthreads();
    s_alpha[tid] = e * inv;
    __syncthreads();

    const int j = tid & 255, seg = tid >> 8;
    float p = 0.f;
    const float* hp = g_hs + (size_t)seg * 256 * HID + j;
    const float* ap = s_alpha + seg * 256;
    for (int t = 0; t < 256; t++) p = fmaf(ap[t], hp[t * HID], p);
    s_red[tid] = p;
    __syncthreads();
    if (tid < 256)
        out[j] = (s_red[j] + s_red[256 + j]) + (s_red[512 + j] + s_red[768 + j]);
}

// ============================================================================
extern "C" void kernel_launch(void* const* d_in, const int* in_sizes, int n_in,
                              void* d_out, int out_size) {
    const float* X = nullptr;
    const float* H = nullptr;
    const float* w_ih = nullptr;
    const float* w_hh = nullptr;
    const float* b_ih = nullptr;
    const float* b_hh = nullptr;
    const float* w_attn = nullptr;
    for (int i = 0; i < n_in; i++) {
        int s = in_sizes[i];
        const float* p = (const float*)d_in[i];
        if (s == N_NODES * IN_CH)      X = p;
        else if (s == N_NODES * T_SEQ) H = p;
        else if (s == G3 * IN_CH)      w_ih = p;
        else if (s == G3 * HID)        w_hh = p;
        else if (s == G3) { if (!b_ih) b_ih = p; else b_hh = p; }  // dict order: b_ih first
        else if (s == HID)             w_attn = p;
    }
    float* out = (float*)d_out;

    k1_kernel<<<dim3(8, K1_NCHUNK), 256>>>(H, X);
    k1_reduce_kernel<<<(T_SEQ * IN_CH) / 256, 256>>>();
    gx_kernel<<<T_SEQ, 256>>>(w_ih, b_ih);

    cudaFuncSetAttribute(gru_kernel, cudaFuncAttributeMaxDynamicSharedMemorySize,
                         GRU_SMEM_BYTES);
    gru_kernel<<<8, 256, GRU_SMEM_BYTES>>>(w_hh, b_hh);

    attn_kernel<<<1, 1024>>>(w_attn, out);
}